// round 13
// baseline (speedup 1.0000x reference)
#include <cuda_runtime.h>

#define BB 8192
#define TT 256
#define FF 16
#define HH 8
#define FUT 8

typedef unsigned long long u64;

__device__ __forceinline__ float tanhm(float x) {
    float y;
    asm("tanh.approx.f32 %0, %1;" : "=f"(y) : "f"(x));
    return y;
}
__device__ __forceinline__ float sigm(float x) {
    return fmaf(0.5f, tanhm(0.5f * x), 0.5f);
}
__device__ __forceinline__ u64 ffma2(u64 a, u64 b, u64 c) {
    u64 d;
    asm("fma.rn.f32x2 %0, %1, %2, %3;" : "=l"(d) : "l"(a), "l"(b), "l"(c));
    return d;
}
__device__ __forceinline__ float hsum2(u64 v) {
    float lo, hi;
    asm("mov.b64 {%0, %1}, %2;" : "=f"(lo), "=f"(hi) : "l"(v));
    return lo + hi;
}
__device__ __forceinline__ float2 unpack2(u64 v) {
    float lo, hi;
    asm("mov.b64 {%0, %1}, %2;" : "=f"(lo), "=f"(hi) : "l"(v));
    return make_float2(lo, hi);
}

// 2 elems/thread, FFMA2, smem weights, pair-double-buffered x (R10 base).
// h-exchange via SMEM instead of shuffles: 1 STS + syncwarp + LDS.128 loads
// that return h already packed as f32x2 pairs (no pack2, no shfl chains).
// Group stride 40 floats -> conflict-free STS and LDS within each warp.

__global__ __launch_bounds__(64) void LSTM_91122026152229_kernel(
    const float* __restrict__ past,   // [B,T,F]
    const float* __restrict__ fut,    // [B,FUT]
    const float* __restrict__ W1, const float* __restrict__ U1, const float* __restrict__ b1,
    const float* __restrict__ W2, const float* __restrict__ U2, const float* __restrict__ b2,
    const float* __restrict__ Wd1, const float* __restrict__ bd1,
    const float* __restrict__ Wd2, const float* __restrict__ bd2,
    const float* __restrict__ Wo, const float* __restrict__ bo,
    float* __restrict__ out)          // [B,4]
{
    __shared__ ulonglong2 sW1if[8 * 8], sW1go[8 * 8];   // k2=0..7
    __shared__ ulonglong2 sU1if[4 * 8], sU1go[4 * 8];   // k2=0..3
    __shared__ ulonglong2 sW2if[4 * 8], sW2go[4 * 8];
    __shared__ ulonglong2 sU2if[4 * 8], sU2go[4 * 8];
    // h exchange buffer: 8 groups x 40 floats (stride 40 => banks 0/8/16/24)
    __shared__ __align__(16) float sh[8 * 40];

    const int tid = threadIdx.x;

    // repack W1 (512 floats): src i = f*32 + g*8 + u
    for (int i = tid; i < 512; i += 64) {
        int f = i >> 5, r = i & 31, gg = r >> 3, uu = r & 7;
        int k2 = f >> 1, odd = f & 1;
        float v = W1[i];
        if (gg < 2)
            ((float*)sW1if)[((k2 * 8 + uu) << 2) + gg * 2 + odd] = v;
        else
            ((float*)sW1go)[((k2 * 8 + uu) << 2) + (gg - 2) * 2 + odd] = v;
    }
    // repack U1, W2, U2 (256 floats each)
    for (int i = tid; i < 256; i += 64) {
        int k = i >> 5, r = i & 31, gg = r >> 3, uu = r & 7;
        int k2 = k >> 1, odd = k & 1;
        int fo = ((k2 * 8 + uu) << 2) + ((gg & 1) * 2) + odd;
        float vU1 = U1[i], vW2 = W2[i], vU2 = U2[i];
        if (gg < 2) {
            ((float*)sU1if)[fo] = vU1;
            ((float*)sW2if)[fo] = vW2;
            ((float*)sU2if)[fo] = vU2;
        } else {
            ((float*)sU1go)[fo] = vU1;
            ((float*)sW2go)[fo] = vW2;
            ((float*)sU2go)[fo] = vU2;
        }
    }
    __syncthreads();

    const int g      = blockIdx.x * 64 + tid;
    const int group8 = g >> 3;
    const int u      = g & 7;
    const int gl     = tid >> 3;           // local group 0..7
    const int gbase  = gl * 40;            // smem base for this group

    const int eA = group8 * 2;
    const int eB = eA + 1;

    const float bi1 = b1[u], bf1 = b1[u + 8], bg1 = b1[u + 16], bq1 = b1[u + 24];
    const float bi2 = b2[u], bf2 = b2[u + 8], bg2 = b2[u + 16], bq2 = b2[u + 24];

    const ulonglong2* __restrict__ xpA = (const ulonglong2*)(past + (size_t)eA * (TT * FF));
    const ulonglong2* __restrict__ xpB = (const ulonglong2*)(past + (size_t)eB * (TT * FF));

    float c1A = 0.f, c2A = 0.f;
    float c1B = 0.f, c2B = 0.f;
    u64 hp1A[4], hp1B[4], hp2A[4], hp2B[4];
    #pragma unroll
    for (int j = 0; j < 4; j++) { hp1A[j] = 0ULL; hp1B[j] = 0ULL; hp2A[j] = 0ULL; hp2B[j] = 0ULL; }

    // one LSTM timestep for both elements
    auto step = [&](const ulonglong2* cA4, const ulonglong2* cB4) {
        const u64 xqA[8] = { cA4[0].x, cA4[0].y, cA4[1].x, cA4[1].y,
                             cA4[2].x, cA4[2].y, cA4[3].x, cA4[3].y };
        const u64 xqB[8] = { cB4[0].x, cB4[0].y, cB4[1].x, cB4[1].y,
                             cB4[2].x, cB4[2].y, cB4[3].x, cB4[3].y };

        // ---- layer 1 ----
        u64 aiA = 0, afA = 0, agA = 0, aoA = 0;
        u64 aiB = 0, afB = 0, agB = 0, aoB = 0;
        #pragma unroll
        for (int k2 = 0; k2 < 8; k2++) {
            const ulonglong2 wif = sW1if[k2 * 8 + u];
            const ulonglong2 wgo = sW1go[k2 * 8 + u];
            const u64 xA = xqA[k2], xB = xqB[k2];
            aiA = ffma2(xA, wif.x, aiA);  aiB = ffma2(xB, wif.x, aiB);
            afA = ffma2(xA, wif.y, afA);  afB = ffma2(xB, wif.y, afB);
            agA = ffma2(xA, wgo.x, agA);  agB = ffma2(xB, wgo.x, agB);
            aoA = ffma2(xA, wgo.y, aoA);  aoB = ffma2(xB, wgo.y, aoB);
        }
        #pragma unroll
        for (int k2 = 0; k2 < 4; k2++) {
            const ulonglong2 wif = sU1if[k2 * 8 + u];
            const ulonglong2 wgo = sU1go[k2 * 8 + u];
            const u64 hA = hp1A[k2], hB = hp1B[k2];
            aiA = ffma2(hA, wif.x, aiA);  aiB = ffma2(hB, wif.x, aiB);
            afA = ffma2(hA, wif.y, afA);  afB = ffma2(hB, wif.y, afB);
            agA = ffma2(hA, wgo.x, agA);  agB = ffma2(hB, wgo.x, agB);
            aoA = ffma2(hA, wgo.y, aoA);  aoB = ffma2(hB, wgo.y, aoB);
        }
        float h1A, h1B;
        {
            const float ziA = hsum2(aiA) + bi1, zfA = hsum2(afA) + bf1;
            const float zgA = hsum2(agA) + bg1, zoA = hsum2(aoA) + bq1;
            c1A = fmaf(sigm(zfA), c1A, sigm(ziA) * tanhm(zgA));
            h1A = sigm(zoA) * tanhm(c1A);
            const float ziB = hsum2(aiB) + bi1, zfB = hsum2(afB) + bf1;
            const float zgB = hsum2(agB) + bg1, zoB = hsum2(aoB) + bq1;
            c1B = fmaf(sigm(zfB), c1B, sigm(ziB) * tanhm(zgB));
            h1B = sigm(zoB) * tanhm(c1B);
        }
        // ---- h1 exchange via smem: STS + syncwarp + packed LDS.128 ----
        sh[gbase + u]     = h1A;
        sh[gbase + 8 + u] = h1B;
        __syncwarp();
        {
            const ulonglong2 pA0 = *(const ulonglong2*)&sh[gbase + 0];
            const ulonglong2 pA1 = *(const ulonglong2*)&sh[gbase + 4];
            const ulonglong2 pB0 = *(const ulonglong2*)&sh[gbase + 8];
            const ulonglong2 pB1 = *(const ulonglong2*)&sh[gbase + 12];
            hp1A[0] = pA0.x; hp1A[1] = pA0.y; hp1A[2] = pA1.x; hp1A[3] = pA1.y;
            hp1B[0] = pB0.x; hp1B[1] = pB0.y; hp1B[2] = pB1.x; hp1B[3] = pB1.y;
        }

        // ---- layer 2 ----
        u64 yiA = 0, yfA = 0, ygA = 0, yoA = 0;
        u64 yiB = 0, yfB = 0, ygB = 0, yoB = 0;
        #pragma unroll
        for (int k2 = 0; k2 < 4; k2++) {
            const ulonglong2 wif = sW2if[k2 * 8 + u];
            const ulonglong2 wgo = sW2go[k2 * 8 + u];
            const u64 hA = hp1A[k2], hB = hp1B[k2];
            yiA = ffma2(hA, wif.x, yiA);  yiB = ffma2(hB, wif.x, yiB);
            yfA = ffma2(hA, wif.y, yfA);  yfB = ffma2(hB, wif.y, yfB);
            ygA = ffma2(hA, wgo.x, ygA);  ygB = ffma2(hB, wgo.x, ygB);
            yoA = ffma2(hA, wgo.y, yoA);  yoB = ffma2(hB, wgo.y, yoB);
        }
        #pragma unroll
        for (int k2 = 0; k2 < 4; k2++) {
            const ulonglong2 wif = sU2if[k2 * 8 + u];
            const ulonglong2 wgo = sU2go[k2 * 8 + u];
            const u64 hA = hp2A[k2], hB = hp2B[k2];
            yiA = ffma2(hA, wif.x, yiA);  yiB = ffma2(hB, wif.x, yiB);
            yfA = ffma2(hA, wif.y, yfA);  yfB = ffma2(hB, wif.y, yfB);
            ygA = ffma2(hA, wgo.x, ygA);  ygB = ffma2(hB, wgo.x, ygB);
            yoA = ffma2(hA, wgo.y, yoA);  yoB = ffma2(hB, wgo.y, yoB);
        }
        float h2A, h2B;
        {
            const float ziA = hsum2(yiA) + bi2, zfA = hsum2(yfA) + bf2;
            const float zgA = hsum2(ygA) + bg2, zoA = hsum2(yoA) + bq2;
            c2A = fmaf(sigm(zfA), c2A, sigm(ziA) * tanhm(zgA));
            h2A = sigm(zoA) * tanhm(c2A);
            const float ziB = hsum2(yiB) + bi2, zfB = hsum2(yfB) + bf2;
            const float zgB = hsum2(ygB) + bg2, zoB = hsum2(yoB) + bq2;
            c2B = fmaf(sigm(zfB), c2B, sigm(ziB) * tanhm(zgB));
            h2B = sigm(zoB) * tanhm(c2B);
        }
        // ---- h2 exchange via smem ----
        sh[gbase + 16 + u] = h2A;
        sh[gbase + 24 + u] = h2B;
        __syncwarp();
        {
            const ulonglong2 qA0 = *(const ulonglong2*)&sh[gbase + 16];
            const ulonglong2 qA1 = *(const ulonglong2*)&sh[gbase + 20];
            const ulonglong2 qB0 = *(const ulonglong2*)&sh[gbase + 24];
            const ulonglong2 qB1 = *(const ulonglong2*)&sh[gbase + 28];
            hp2A[0] = qA0.x; hp2A[1] = qA0.y; hp2A[2] = qA1.x; hp2A[3] = qA1.y;
            hp2B[0] = qB0.x; hp2B[1] = qB0.y; hp2B[2] = qB1.x; hp2B[3] = qB1.y;
        }
    };

    // current pair buffer: x[t], x[t+1] = 8 ulonglong2 per element
    ulonglong2 cA[8], cB[8];
    #pragma unroll
    for (int j = 0; j < 8; j++) { cA[j] = xpA[j]; cB[j] = xpB[j]; }

    #pragma unroll 1
    for (int t = 0; t < TT; t += 2) {
        // prefetch NEXT pair (t+2, t+3): load->use spans two timestep bodies
        const int tn = (t + 2 < TT) ? (t + 2) : t;
        ulonglong2 nA[8], nB[8];
        #pragma unroll
        for (int j = 0; j < 8; j++) {
            nA[j] = xpA[tn * 4 + j];
            nB[j] = xpB[tn * 4 + j];
        }

        step(cA + 0, cB + 0);   // timestep t
        step(cA + 4, cB + 4);   // timestep t+1

        #pragma unroll
        for (int j = 0; j < 8; j++) { cA[j] = nA[j]; cB[j] = nB[j]; }
    }

    // ---- MLP head for both elements ----
    float h2sA[8], h2sB[8];
    #pragma unroll
    for (int k2 = 0; k2 < 4; k2++) {
        const float2 pA = unpack2(hp2A[k2]);
        const float2 pB = unpack2(hp2B[k2]);
        h2sA[2 * k2] = pA.x; h2sA[2 * k2 + 1] = pA.y;
        h2sB[2 * k2] = pB.x; h2sB[2 * k2 + 1] = pB.y;
    }

    float d1A = bd1[u], d1B = d1A;
    #pragma unroll
    for (int k = 0; k < 8; k++) {
        const float wk = Wd1[k * 8 + u];
        d1A = fmaf(h2sA[k], wk, d1A);
        d1B = fmaf(h2sB[k], wk, d1B);
    }
    const float* __restrict__ fpA = fut + (size_t)eA * FUT;
    const float* __restrict__ fpB = fut + (size_t)eB * FUT;
    #pragma unroll
    for (int k = 0; k < 8; k++) {
        const float wk = Wd1[(8 + k) * 8 + u];
        d1A = fmaf(fpA[k], wk, d1A);
        d1B = fmaf(fpB[k], wk, d1B);
    }
    d1A = fmaxf(d1A, 0.f);
    d1B = fmaxf(d1B, 0.f);

    // d1 exchange via smem (reuse the h buffer slots)
    sh[gbase + u]     = d1A;
    sh[gbase + 8 + u] = d1B;
    __syncwarp();
    float d2A = bd2[u], d2B = d2A;
    #pragma unroll
    for (int k = 0; k < 8; k++) {
        const float wk = Wd2[k * 8 + u];
        d2A = fmaf(sh[gbase + k], wk, d2A);
        d2B = fmaf(sh[gbase + 8 + k], wk, d2B);
    }
    d2A = fmaxf(d2A, 0.f);
    d2B = fmaxf(d2B, 0.f);

    __syncwarp();
    sh[gbase + 16 + u] = d2A;
    sh[gbase + 24 + u] = d2B;
    __syncwarp();
    if (u < 4) {
        float oA = bo[u], oB = bo[u];
        #pragma unroll
        for (int k = 0; k < 8; k++) {
            const float wk = Wo[k * 4 + u];
            oA = fmaf(sh[gbase + 16 + k], wk, oA);
            oB = fmaf(sh[gbase + 24 + k], wk, oB);
        }
        out[(size_t)eA * 4 + u] = oA;
        out[(size_t)eB * 4 + u] = oB;
    }
}

extern "C" void kernel_launch(void* const* d_in, const int* in_sizes, int n_in,
                              void* d_out, int out_size) {
    const float* past = (const float*)d_in[1];
    const float* fut  = (const float*)d_in[2];
    const float* W1   = (const float*)d_in[3];
    const float* U1   = (const float*)d_in[4];
    const float* b1   = (const float*)d_in[5];
    const float* W2   = (const float*)d_in[6];
    const float* U2   = (const float*)d_in[7];
    const float* b2   = (const float*)d_in[8];
    const float* Wd1  = (const float*)d_in[9];
    const float* bd1  = (const float*)d_in[10];
    const float* Wd2  = (const float*)d_in[11];
    const float* bd2  = (const float*)d_in[12];
    const float* Wo   = (const float*)d_in[13];
    const float* bo   = (const float*)d_in[14];

    // 32768 threads: 2 elements per thread, single wave (512 blocks)
    LSTM_91122026152229_kernel<<<(BB * HH / 2) / 64, 64>>>(
        past, fut, W1, U1, b1, W2, U2, b2, Wd1, bd1, Wd2, bd2, Wo, bo,
        (float*)d_out);
}

// round 14
// speedup vs baseline: 1.2184x; 1.2184x over previous
#include <cuda_runtime.h>

#define BB 8192
#define TT 256
#define FF 16
#define HH 8
#define FUT 8

typedef unsigned long long u64;

__device__ __forceinline__ float tanhm(float x) {
    float y;
    asm("tanh.approx.f32 %0, %1;" : "=f"(y) : "f"(x));
    return y;
}
__device__ __forceinline__ float sigm(float x) {
    return fmaf(0.5f, tanhm(0.5f * x), 0.5f);
}
__device__ __forceinline__ u64 ffma2(u64 a, u64 b, u64 c) {
    u64 d;
    asm("fma.rn.f32x2 %0, %1, %2, %3;" : "=l"(d) : "l"(a), "l"(b), "l"(c));
    return d;
}
__device__ __forceinline__ u64 pack2(float lo, float hi) {
    u64 r;
    asm("mov.b64 %0, {%1, %2};" : "=l"(r) : "f"(lo), "f"(hi));
    return r;
}
__device__ __forceinline__ float hsum2(u64 v) {
    float lo, hi;
    asm("mov.b64 {%0, %1}, %2;" : "=f"(lo), "=f"(hi) : "l"(v));
    return lo + hi;
}
__device__ __forceinline__ float2 unpack2(u64 v) {
    float lo, hi;
    asm("mov.b64 {%0, %1}, %2;" : "=f"(lo), "=f"(hi) : "l"(v));
    return make_float2(lo, hi);
}
__device__ __forceinline__ void cpa16(unsigned dst, const void* src) {
    asm volatile("cp.async.ca.shared.global [%0], [%1], 16;\n"
                 :: "r"(dst), "l"(src) : "memory");
}
__device__ __forceinline__ void cpa_commit() {
    asm volatile("cp.async.commit_group;\n" ::: "memory");
}
__device__ __forceinline__ void cpa_wait3() {
    asm volatile("cp.async.wait_group 3;\n" ::: "memory");
}

// 2 elems/thread. Recurrent weights U1, W2, U2 in REGISTERS (48 u64).
// W1 in smem (k2-paired). x staged through a 4-deep cp.async ring in smem
// (no x registers, no LDG in the loop) -> register slack for scheduling.

__global__ __launch_bounds__(64) void LSTM_91122026152229_kernel(
    const float* __restrict__ past,   // [B,T,F]
    const float* __restrict__ fut,    // [B,FUT]
    const float* __restrict__ W1, const float* __restrict__ U1, const float* __restrict__ b1,
    const float* __restrict__ W2, const float* __restrict__ U2, const float* __restrict__ b2,
    const float* __restrict__ Wd1, const float* __restrict__ bd1,
    const float* __restrict__ Wd2, const float* __restrict__ bd2,
    const float* __restrict__ Wo, const float* __restrict__ bo,
    float* __restrict__ out)          // [B,4]
{
    __shared__ ulonglong2 sW1if[8 * 8], sW1go[8 * 8];        // k2-paired W1
    // x ring: 4 slots x 16 elems x 20 floats (80B stride: conflict-free)
    __shared__ __align__(16) float sx[4 * 16 * 20];

    const int tid = threadIdx.x;

    // repack W1 (512 floats): src i = f*32 + g*8 + u
    for (int i = tid; i < 512; i += 64) {
        int f = i >> 5, r = i & 31, gg = r >> 3, uu = r & 7;
        int k2 = f >> 1, odd = f & 1;
        float v = W1[i];
        if (gg < 2)
            ((float*)sW1if)[((k2 * 8 + uu) << 2) + gg * 2 + odd] = v;
        else
            ((float*)sW1go)[((k2 * 8 + uu) << 2) + (gg - 2) * 2 + odd] = v;
    }
    __syncthreads();

    const int g      = blockIdx.x * 64 + tid;
    const int group8 = g >> 3;
    const int u      = g & 7;
    const int gl     = tid >> 3;          // local group 0..7

    const int eA = group8 * 2;
    const int eB = eA + 1;

    // ---- recurrent weights into registers (k-paired f32x2): 48 u64 ----
    u64 wU1[4][4], wW2[4][4], wU2[4][4];
    #pragma unroll
    for (int k2 = 0; k2 < 4; k2++)
        #pragma unroll
        for (int gg = 0; gg < 4; gg++) {
            wU1[k2][gg] = pack2(U1[(2 * k2) * 32 + gg * 8 + u],
                                U1[(2 * k2 + 1) * 32 + gg * 8 + u]);
            wW2[k2][gg] = pack2(W2[(2 * k2) * 32 + gg * 8 + u],
                                W2[(2 * k2 + 1) * 32 + gg * 8 + u]);
            wU2[k2][gg] = pack2(U2[(2 * k2) * 32 + gg * 8 + u],
                                U2[(2 * k2 + 1) * 32 + gg * 8 + u]);
        }

    const float bi1 = b1[u], bf1 = b1[u + 8], bg1 = b1[u + 16], bq1 = b1[u + 24];
    const float bi2 = b2[u], bf2 = b2[u + 8], bg2 = b2[u + 16], bq2 = b2[u + 24];

    // ---- cp.async producer setup: thread loads 16B of elem (tid>>2), chunk (tid&3) ----
    const int pe = tid >> 2;              // elem-in-block 0..15 (warp-local mapping)
    const int pq = tid & 3;               // 16B chunk 0..3
    const float* gsrc = past + (size_t)(blockIdx.x * 16 + pe) * (TT * FF) + pq * 4;
    const unsigned sxa = (unsigned)__cvta_generic_to_shared(sx);
    const unsigned pdst = sxa + (unsigned)(pe * 20 + pq * 4) * 4u;

    // preload stages for t = 0,1,2
    #pragma unroll
    for (int s = 0; s < 3; s++) {
        cpa16(pdst + (unsigned)(s * 320 * 4), gsrc + s * 16);
        cpa_commit();
    }

    float c1A = 0.f, c2A = 0.f, c1B = 0.f, c2B = 0.f;
    u64 hp1A[4], hp1B[4], hp2A[4], hp2B[4];
    #pragma unroll
    for (int j = 0; j < 4; j++) { hp1A[j] = 0ULL; hp1B[j] = 0ULL; hp2A[j] = 0ULL; hp2B[j] = 0ULL; }

    const int lane  = tid & 31;
    const int base8 = lane & 24;

    #pragma unroll 1
    for (int t = 0; t < TT; t++) {
        // produce x for step t+3 into slot (t+3)&3
        const int tn = (t + 3 < TT) ? (t + 3) : (TT - 1);
        cpa16(pdst + (unsigned)(((t + 3) & 3) * 320 * 4), gsrc + tn * 16);
        cpa_commit();
        cpa_wait3();         // group issued at t-3 (data for step t) complete
        __syncwarp();

        // consume x[t] from slot t&3 (packed f32x2 pairs straight from LDS.128)
        const float* xs = sx + (t & 3) * 320;
        const ulonglong2* xAp = (const ulonglong2*)(xs + (gl * 2) * 20);
        const ulonglong2* xBp = (const ulonglong2*)(xs + (gl * 2 + 1) * 20);
        const ulonglong2 xA0 = xAp[0], xA1 = xAp[1], xA2 = xAp[2], xA3 = xAp[3];
        const ulonglong2 xB0 = xBp[0], xB1 = xBp[1], xB2 = xBp[2], xB3 = xBp[3];
        const u64 xqA[8] = { xA0.x, xA0.y, xA1.x, xA1.y, xA2.x, xA2.y, xA3.x, xA3.y };
        const u64 xqB[8] = { xB0.x, xB0.y, xB1.x, xB1.y, xB2.x, xB2.y, xB3.x, xB3.y };

        // ---- layer 1: x-part from smem W1, recurrent part from reg U1 ----
        u64 aiA = 0, afA = 0, agA = 0, aoA = 0;
        u64 aiB = 0, afB = 0, agB = 0, aoB = 0;
        #pragma unroll
        for (int k2 = 0; k2 < 8; k2++) {
            const ulonglong2 wif = sW1if[k2 * 8 + u];
            const ulonglong2 wgo = sW1go[k2 * 8 + u];
            const u64 xA = xqA[k2], xB = xqB[k2];
            aiA = ffma2(xA, wif.x, aiA);  aiB = ffma2(xB, wif.x, aiB);
            afA = ffma2(xA, wif.y, afA);  afB = ffma2(xB, wif.y, afB);
            agA = ffma2(xA, wgo.x, agA);  agB = ffma2(xB, wgo.x, agB);
            aoA = ffma2(xA, wgo.y, aoA);  aoB = ffma2(xB, wgo.y, aoB);
        }
        #pragma unroll
        for (int k2 = 0; k2 < 4; k2++) {
            const u64 hA = hp1A[k2], hB = hp1B[k2];
            aiA = ffma2(hA, wU1[k2][0], aiA);  aiB = ffma2(hB, wU1[k2][0], aiB);
            afA = ffma2(hA, wU1[k2][1], afA);  afB = ffma2(hB, wU1[k2][1], afB);
            agA = ffma2(hA, wU1[k2][2], agA);  agB = ffma2(hB, wU1[k2][2], agB);
            aoA = ffma2(hA, wU1[k2][3], aoA);  aoB = ffma2(hB, wU1[k2][3], aoB);
        }
        float h1A, h1B;
        {
            const float ziA = hsum2(aiA) + bi1, zfA = hsum2(afA) + bf1;
            const float zgA = hsum2(agA) + bg1, zoA = hsum2(aoA) + bq1;
            c1A = fmaf(sigm(zfA), c1A, sigm(ziA) * tanhm(zgA));
            h1A = sigm(zoA) * tanhm(c1A);
            const float ziB = hsum2(aiB) + bi1, zfB = hsum2(afB) + bf1;
            const float zgB = hsum2(agB) + bg1, zoB = hsum2(aoB) + bq1;
            c1B = fmaf(sigm(zfB), c1B, sigm(ziB) * tanhm(zgB));
            h1B = sigm(zoB) * tanhm(c1B);
        }
        #pragma unroll
        for (int k2 = 0; k2 < 4; k2++) {
            const float aA = __shfl_sync(0xffffffffu, h1A, base8 + 2 * k2);
            const float bA = __shfl_sync(0xffffffffu, h1A, base8 + 2 * k2 + 1);
            const float aB = __shfl_sync(0xffffffffu, h1B, base8 + 2 * k2);
            const float bB = __shfl_sync(0xffffffffu, h1B, base8 + 2 * k2 + 1);
            hp1A[k2] = pack2(aA, bA);
            hp1B[k2] = pack2(aB, bB);
        }

        // ---- layer 2: all weights in registers ----
        u64 yiA = 0, yfA = 0, ygA = 0, yoA = 0;
        u64 yiB = 0, yfB = 0, ygB = 0, yoB = 0;
        #pragma unroll
        for (int k2 = 0; k2 < 4; k2++) {
            const u64 hA = hp1A[k2], hB = hp1B[k2];
            yiA = ffma2(hA, wW2[k2][0], yiA);  yiB = ffma2(hB, wW2[k2][0], yiB);
            yfA = ffma2(hA, wW2[k2][1], yfA);  yfB = ffma2(hB, wW2[k2][1], yfB);
            ygA = ffma2(hA, wW2[k2][2], ygA);  ygB = ffma2(hB, wW2[k2][2], ygB);
            yoA = ffma2(hA, wW2[k2][3], yoA);  yoB = ffma2(hB, wW2[k2][3], yoB);
        }
        #pragma unroll
        for (int k2 = 0; k2 < 4; k2++) {
            const u64 hA = hp2A[k2], hB = hp2B[k2];
            yiA = ffma2(hA, wU2[k2][0], yiA);  yiB = ffma2(hB, wU2[k2][0], yiB);
            yfA = ffma2(hA, wU2[k2][1], yfA);  yfB = ffma2(hB, wU2[k2][1], yfB);
            ygA = ffma2(hA, wU2[k2][2], ygA);  ygB = ffma2(hB, wU2[k2][2], ygB);
            yoA = ffma2(hA, wU2[k2][3], yoA);  yoB = ffma2(hB, wU2[k2][3], yoB);
        }
        float h2A, h2B;
        {
            const float ziA = hsum2(yiA) + bi2, zfA = hsum2(yfA) + bf2;
            const float zgA = hsum2(ygA) + bg2, zoA = hsum2(yoA) + bq2;
            c2A = fmaf(sigm(zfA), c2A, sigm(ziA) * tanhm(zgA));
            h2A = sigm(zoA) * tanhm(c2A);
            const float ziB = hsum2(yiB) + bi2, zfB = hsum2(yfB) + bf2;
            const float zgB = hsum2(ygB) + bg2, zoB = hsum2(yoB) + bq2;
            c2B = fmaf(sigm(zfB), c2B, sigm(ziB) * tanhm(zgB));
            h2B = sigm(zoB) * tanhm(c2B);
        }
        #pragma unroll
        for (int k2 = 0; k2 < 4; k2++) {
            const float aA = __shfl_sync(0xffffffffu, h2A, base8 + 2 * k2);
            const float bA = __shfl_sync(0xffffffffu, h2A, base8 + 2 * k2 + 1);
            const float aB = __shfl_sync(0xffffffffu, h2B, base8 + 2 * k2);
            const float bB = __shfl_sync(0xffffffffu, h2B, base8 + 2 * k2 + 1);
            hp2A[k2] = pack2(aA, bA);
            hp2B[k2] = pack2(aB, bB);
        }
    }

    // ---- MLP head for both elements ----
    float h2sA[8], h2sB[8];
    #pragma unroll
    for (int k2 = 0; k2 < 4; k2++) {
        const float2 pA = unpack2(hp2A[k2]);
        const float2 pB = unpack2(hp2B[k2]);
        h2sA[2 * k2] = pA.x; h2sA[2 * k2 + 1] = pA.y;
        h2sB[2 * k2] = pB.x; h2sB[2 * k2 + 1] = pB.y;
    }

    float d1A = bd1[u], d1B = d1A;
    #pragma unroll
    for (int k = 0; k < 8; k++) {
        const float wk = Wd1[k * 8 + u];
        d1A = fmaf(h2sA[k], wk, d1A);
        d1B = fmaf(h2sB[k], wk, d1B);
    }
    const float* __restrict__ fpA = fut + (size_t)eA * FUT;
    const float* __restrict__ fpB = fut + (size_t)eB * FUT;
    #pragma unroll
    for (int k = 0; k < 8; k++) {
        const float wk = Wd1[(8 + k) * 8 + u];
        d1A = fmaf(fpA[k], wk, d1A);
        d1B = fmaf(fpB[k], wk, d1B);
    }
    d1A = fmaxf(d1A, 0.f);
    d1B = fmaxf(d1B, 0.f);

    float d2A = bd2[u], d2B = d2A;
    #pragma unroll
    for (int k = 0; k < 8; k++) {
        const float wk = Wd2[k * 8 + u];
        const float d1kA = __shfl_sync(0xffffffffu, d1A, base8 + k);
        const float d1kB = __shfl_sync(0xffffffffu, d1B, base8 + k);
        d2A = fmaf(d1kA, wk, d2A);
        d2B = fmaf(d1kB, wk, d2B);
    }
    d2A = fmaxf(d2A, 0.f);
    d2B = fmaxf(d2B, 0.f);

    float oA = (u < 4) ? bo[u] : 0.f;
    float oB = oA;
    #pragma unroll
    for (int k = 0; k < 8; k++) {
        const float wk = (u < 4) ? Wo[k * 4 + u] : 0.f;
        const float d2kA = __shfl_sync(0xffffffffu, d2A, base8 + k);
        const float d2kB = __shfl_sync(0xffffffffu, d2B, base8 + k);
        oA = fmaf(d2kA, wk, oA);
        oB = fmaf(d2kB, wk, oB);
    }
    if (u < 4) {
        out[(size_t)eA * 4 + u] = oA;
        out[(size_t)eB * 4 + u] = oB;
    }
}

extern "C" void kernel_launch(void* const* d_in, const int* in_sizes, int n_in,
                              void* d_out, int out_size) {
    const float* past = (const float*)d_in[1];
    const float* fut  = (const float*)d_in[2];
    const float* W1   = (const float*)d_in[3];
    const float* U1   = (const float*)d_in[4];
    const float* b1   = (const float*)d_in[5];
    const float* W2   = (const float*)d_in[6];
    const float* U2   = (const float*)d_in[7];
    const float* b2   = (const float*)d_in[8];
    const float* Wd1  = (const float*)d_in[9];
    const float* bd1  = (const float*)d_in[10];
    const float* Wd2  = (const float*)d_in[11];
    const float* bd2  = (const float*)d_in[12];
    const float* Wo   = (const float*)d_in[13];
    const float* bo   = (const float*)d_in[14];

    // 32768 threads: 2 elements per thread, single wave (512 blocks)
    LSTM_91122026152229_kernel<<<(BB * HH / 2) / 64, 64>>>(
        past, fut, W1, U1, b1, W2, U2, b2, Wd1, bd1, Wd2, bd2, Wo, bo,
        (float*)d_out);
}